// round 2
// baseline (speedup 1.0000x reference)
#include <cuda_runtime.h>

#define DIMV 768
#define NHEAD 16
#define PH 48
#define BATCH 4
#define TSEQ 2048
#define MTOT (BATCH * TSEQ)   // 8192
#define NQKV (3 * DIMV)       // 2304

// Scratch (allocation-free rule: __device__ globals)
__device__ float g_qkv[MTOT * NQKV];   // (8192, 2304)
__device__ float g_att[MTOT * DIMV];   // (8192, 768)

// ---------------------------------------------------------------------------
// Tiled fp32 GEMM with bias: C[M,N] = A[M,K] @ B[K,N] + bias[N]
// BM=BN=64, BK=16, 256 threads, 4x4 micro-tile. M%64==0, N%64==0, K%16==0.
// ---------------------------------------------------------------------------
__global__ void __launch_bounds__(256) gemm_bias_kernel(
    const float* __restrict__ A, const float* __restrict__ B,
    const float* __restrict__ bias, float* __restrict__ C,
    int M, int N, int K)
{
    __shared__ float As[16][64];   // transposed A tile
    __shared__ float Bs[16][64];

    const int tid = threadIdx.x;
    const int m0 = blockIdx.y * 64;
    const int n0 = blockIdx.x * 64;
    const int ty = tid >> 4;        // 0..15
    const int tx = tid & 15;        // 0..15

    // load indices
    const int arow = tid >> 2;            // 0..63
    const int ac4  = (tid & 3) << 2;      // 0,4,8,12
    const int brow = tid >> 4;            // 0..15
    const int bc4  = (tid & 15) << 2;     // 0..60

    float acc[4][4] = {};

    for (int k0 = 0; k0 < K; k0 += 16) {
        float4 av = *(const float4*)&A[(long)(m0 + arow) * K + k0 + ac4];
        As[ac4 + 0][arow] = av.x;
        As[ac4 + 1][arow] = av.y;
        As[ac4 + 2][arow] = av.z;
        As[ac4 + 3][arow] = av.w;
        float4 bv = *(const float4*)&B[(long)(k0 + brow) * N + n0 + bc4];
        *(float4*)&Bs[brow][bc4] = bv;
        __syncthreads();

        #pragma unroll
        for (int k = 0; k < 16; k++) {
            float4 a = *(const float4*)&As[k][ty * 4];
            float4 b = *(const float4*)&Bs[k][tx * 4];
            float ar[4] = {a.x, a.y, a.z, a.w};
            float br[4] = {b.x, b.y, b.z, b.w};
            #pragma unroll
            for (int i = 0; i < 4; i++)
                #pragma unroll
                for (int j = 0; j < 4; j++)
                    acc[i][j] += ar[i] * br[j];
        }
        __syncthreads();
    }

    const int col = n0 + tx * 4;
    float4 bb = *(const float4*)&bias[col];
    #pragma unroll
    for (int i = 0; i < 4; i++) {
        const int row = m0 + ty * 4 + i;
        float4 o = make_float4(acc[i][0] + bb.x, acc[i][1] + bb.y,
                               acc[i][2] + bb.z, acc[i][3] + bb.w);
        *(float4*)&C[(long)row * N + col] = o;
    }
}

// ---------------------------------------------------------------------------
// Flash attention: one thread owns one query row (q[48], o[48] in regs).
// grid = (TSEQ/128, BATCH*NHEAD), block = 128 threads.
// qkv layout: row (b*T+t), head h at col h*144: [q:0..47][k:48..95][v:96..143]
// out layout: (b*T+t, h*48+d)
// ---------------------------------------------------------------------------
__global__ void __launch_bounds__(128) attn_kernel(
    const float* __restrict__ qkv, float* __restrict__ out)
{
    __shared__ float Ks[64][PH];
    __shared__ float Vs[64][PH];

    const int bh = blockIdx.y;
    const int b = bh / NHEAD;
    const int h = bh % NHEAD;
    const int tid = threadIdx.x;                 // 0..127
    const int qrow = blockIdx.x * 128 + tid;     // 0..T-1

    const float scale = 0.14433756729740643f;    // 1/sqrt(48)
    const long headCol = (long)h * (3 * PH);

    // Load & pre-scale q
    float q[PH];
    {
        const float* qptr = qkv + ((long)(b * TSEQ + qrow)) * NQKV + headCol;
        #pragma unroll
        for (int d4 = 0; d4 < PH / 4; d4++) {
            float4 v = *(const float4*)&qptr[d4 * 4];
            q[4 * d4 + 0] = v.x * scale;
            q[4 * d4 + 1] = v.y * scale;
            q[4 * d4 + 2] = v.z * scale;
            q[4 * d4 + 3] = v.w * scale;
        }
    }

    float o[PH] = {};
    float mi = -1e30f;
    float l = 0.f;

    for (int kb = 0; kb < TSEQ; kb += 64) {
        // cooperative K/V tile load: 64 rows x 12 float4 per tile
        for (int idx = tid; idx < 64 * 12; idx += 128) {
            const int r  = idx / 12;
            const int c4 = idx % 12;
            const float* src = qkv + ((long)(b * TSEQ + kb + r)) * NQKV + headCol;
            *(float4*)&Ks[r][c4 * 4] = *(const float4*)&src[PH + c4 * 4];
            *(float4*)&Vs[r][c4 * 4] = *(const float4*)&src[2 * PH + c4 * 4];
        }
        __syncthreads();

        #pragma unroll 1
        for (int j = 0; j < 64; j++) {
            const float4* kr = (const float4*)Ks[j];
            float s0 = 0.f, s1 = 0.f, s2 = 0.f, s3 = 0.f;
            #pragma unroll
            for (int d4 = 0; d4 < 12; d4++) {
                float4 kv = kr[d4];
                s0 += q[4 * d4 + 0] * kv.x;
                s1 += q[4 * d4 + 1] * kv.y;
                s2 += q[4 * d4 + 2] * kv.z;
                s3 += q[4 * d4 + 3] * kv.w;
            }
            float s = (s0 + s1) + (s2 + s3);

            if (s > mi) {                         // lazy rescale (rare)
                float corr = __expf(mi - s);
                mi = s;
                l *= corr;
                #pragma unroll
                for (int d = 0; d < PH; d++) o[d] *= corr;
            }
            float p = __expf(s - mi);
            l += p;

            const float4* vr = (const float4*)Vs[j];
            #pragma unroll
            for (int d4 = 0; d4 < 12; d4++) {
                float4 vv = vr[d4];
                o[4 * d4 + 0] += p * vv.x;
                o[4 * d4 + 1] += p * vv.y;
                o[4 * d4 + 2] += p * vv.z;
                o[4 * d4 + 3] += p * vv.w;
            }
        }
        __syncthreads();
    }

    const float inv_l = 1.0f / l;
    float* optr = out + ((long)(b * TSEQ + qrow)) * DIMV + (long)h * PH;
    #pragma unroll
    for (int d4 = 0; d4 < 12; d4++) {
        float4 v = make_float4(o[4 * d4 + 0] * inv_l, o[4 * d4 + 1] * inv_l,
                               o[4 * d4 + 2] * inv_l, o[4 * d4 + 3] * inv_l);
        *(float4*)&optr[d4 * 4] = v;
    }
}

// ---------------------------------------------------------------------------
extern "C" void kernel_launch(void* const* d_in, const int* in_sizes, int n_in,
                              void* d_out, int out_size)
{
    const float* x     = (const float*)d_in[0];
    const float* w_in  = (const float*)d_in[1];
    const float* b_in  = (const float*)d_in[2];
    const float* w_out = (const float*)d_in[3];
    const float* b_out = (const float*)d_in[4];
    float* out = (float*)d_out;

    float* qkv = nullptr;
    float* att = nullptr;
    cudaGetSymbolAddress((void**)&qkv, g_qkv);
    cudaGetSymbolAddress((void**)&att, g_att);

    // 1) QKV projection: (8192,768) @ (768,2304) + b_in
    {
        dim3 grid(NQKV / 64, MTOT / 64);
        gemm_bias_kernel<<<grid, 256>>>(x, w_in, b_in, qkv, MTOT, NQKV, DIMV);
    }

    // 2) Attention
    {
        dim3 grid(TSEQ / 128, BATCH * NHEAD);
        attn_kernel<<<grid, 128>>>(qkv, att);
    }

    // 3) Output projection: (8192,768) @ (768,768) + b_out
    {
        dim3 grid(DIMV / 64, MTOT / 64);
        gemm_bias_kernel<<<grid, 256>>>(att, w_out, b_out, out, MTOT, DIMV, DIMV);
    }
}

// round 3
// speedup vs baseline: 1.1467x; 1.1467x over previous
#include <cuda_runtime.h>

#define DIMV 768
#define NHEAD 16
#define PH 48
#define BATCH 4
#define TSEQ 2048
#define MTOT (BATCH * TSEQ)   // 8192
#define NQKV (3 * DIMV)       // 2304

typedef unsigned long long u64;

// Scratch (allocation-free rule: __device__ globals)
__device__ float g_qkv[MTOT * NQKV];   // (8192, 2304)
__device__ float g_att[MTOT * DIMV];   // (8192, 768)

// ---- packed f32x2 helpers (sm_100+ PTX; ptxas never auto-emits these) ----
__device__ __forceinline__ u64 pk2(float lo, float hi) {
    u64 r; asm("mov.b64 %0,{%1,%2};" : "=l"(r) : "f"(lo), "f"(hi)); return r;
}
__device__ __forceinline__ float2 upk2(u64 v) {
    float2 r; asm("mov.b64 {%0,%1},%2;" : "=f"(r.x), "=f"(r.y) : "l"(v)); return r;
}
__device__ __forceinline__ void fma2(u64& d, u64 a, u64 b) {
    asm("fma.rn.f32x2 %0,%1,%2,%0;" : "+l"(d) : "l"(a), "l"(b));
}
__device__ __forceinline__ void mul2(u64& d, u64 a, u64 b) {
    asm("mul.rn.f32x2 %0,%1,%2;" : "=l"(d) : "l"(a), "l"(b));
}

// ---------------------------------------------------------------------------
// Tiled fp32 GEMM with bias: C[M,N] = A[M,K] @ B[K,N] + bias[N]
// BM=BN=128, BK=16, 256 threads, 8x8 micro-tile, f32x2 packed math,
// register prefetch of the next global tile.
// Requires M%128==0, N%128==0, K%16==0.
// ---------------------------------------------------------------------------
__global__ void __launch_bounds__(256) gemm_bias_kernel(
    const float* __restrict__ A, const float* __restrict__ B,
    const float* __restrict__ bias, float* __restrict__ C,
    int M, int N, int K)
{
    __shared__ float As[16][128];   // transposed A tile: As[k][m]
    __shared__ float Bs[16][128];   // Bs[k][n]

    const int tid = threadIdx.x;
    const int m0 = blockIdx.y * 128;
    const int n0 = blockIdx.x * 128;
    const int ty = tid >> 4;        // 0..15 -> rows ty*8..+7
    const int tx = tid & 15;        // 0..15 -> cols tx*8..+7

    // A load mapping: thread -> row = tid>>1 (0..127), col4 = (tid&1)*8
    const int arow = tid >> 1;
    const int ac  = (tid & 1) * 8;
    // B load mapping: thread -> row = tid>>4 (0..15), col = (tid&15)*8
    const int brow = tid >> 4;
    const int bc   = (tid & 15) * 8;

    const float* Aptr = A + (long)(m0 + arow) * K + ac;
    const float* Bptr = B + (long)brow * N + n0 + bc;

    u64 acc[8][4];
    #pragma unroll
    for (int i = 0; i < 8; i++)
        #pragma unroll
        for (int j = 0; j < 4; j++) acc[i][j] = 0ull;

    // prefetch first tile into registers
    float4 a0 = *(const float4*)(Aptr + 0);
    float4 a1 = *(const float4*)(Aptr + 4);
    float4 b0 = *(const float4*)(Bptr + 0);
    float4 b1 = *(const float4*)(Bptr + 4);

    for (int k0 = 0; k0 < K; k0 += 16) {
        // store prefetched tile to smem (A transposed: scalar STS, conflict-free)
        As[ac + 0][arow] = a0.x; As[ac + 1][arow] = a0.y;
        As[ac + 2][arow] = a0.z; As[ac + 3][arow] = a0.w;
        As[ac + 4][arow] = a1.x; As[ac + 5][arow] = a1.y;
        As[ac + 6][arow] = a1.z; As[ac + 7][arow] = a1.w;
        *(float4*)&Bs[brow][bc + 0] = b0;
        *(float4*)&Bs[brow][bc + 4] = b1;
        __syncthreads();

        // prefetch next tile (global latency hidden under the compute below)
        if (k0 + 16 < K) {
            a0 = *(const float4*)(Aptr + (k0 + 16) + 0);
            a1 = *(const float4*)(Aptr + (k0 + 16) + 4);
            b0 = *(const float4*)(Bptr + (long)(k0 + 16) * N + 0);
            b1 = *(const float4*)(Bptr + (long)(k0 + 16) * N + 4);
        }

        #pragma unroll
        for (int k = 0; k < 16; k++) {
            // b fragment: 8 floats = 4 packed pairs, read directly as u64 pairs
            ulonglong2 bv0 = *(const ulonglong2*)&Bs[k][tx * 8];
            ulonglong2 bv1 = *(const ulonglong2*)&Bs[k][tx * 8 + 4];
            u64 bb[4] = {bv0.x, bv0.y, bv1.x, bv1.y};
            // a fragment: 8 scalars, lane-duplicated
            float4 af0 = *(const float4*)&As[k][ty * 8];
            float4 af1 = *(const float4*)&As[k][ty * 8 + 4];
            float ar[8] = {af0.x, af0.y, af0.z, af0.w, af1.x, af1.y, af1.z, af1.w};
            #pragma unroll
            for (int i = 0; i < 8; i++) {
                u64 aa = pk2(ar[i], ar[i]);
                #pragma unroll
                for (int j = 0; j < 4; j++) fma2(acc[i][j], aa, bb[j]);
            }
        }
        __syncthreads();
    }

    // epilogue: unpack, add bias, store
    const int col = n0 + tx * 8;
    float4 bbias0 = *(const float4*)&bias[col];
    float4 bbias1 = *(const float4*)&bias[col + 4];
    #pragma unroll
    for (int i = 0; i < 8; i++) {
        const int row = m0 + ty * 8 + i;
        float2 c0 = upk2(acc[i][0]);
        float2 c1 = upk2(acc[i][1]);
        float2 c2 = upk2(acc[i][2]);
        float2 c3 = upk2(acc[i][3]);
        float4 o0 = make_float4(c0.x + bbias0.x, c0.y + bbias0.y,
                                c1.x + bbias0.z, c1.y + bbias0.w);
        float4 o1 = make_float4(c2.x + bbias1.x, c2.y + bbias1.y,
                                c3.x + bbias1.z, c3.y + bbias1.w);
        *(float4*)&C[(long)row * N + col + 0] = o0;
        *(float4*)&C[(long)row * N + col + 4] = o1;
    }
}

// ---------------------------------------------------------------------------
// Flash attention, f32x2 packed: one thread owns one query row.
// grid = (TSEQ/128, BATCH*NHEAD), block = 128 threads.
// ---------------------------------------------------------------------------
__global__ void __launch_bounds__(128) attn_kernel(
    const float* __restrict__ qkv, float* __restrict__ out)
{
    __shared__ float Ks[64][PH];
    __shared__ float Vs[64][PH];

    const int bh = blockIdx.y;
    const int b = bh / NHEAD;
    const int h = bh % NHEAD;
    const int tid = threadIdx.x;
    const int qrow = blockIdx.x * 128 + tid;

    const float scale = 0.14433756729740643f;    // 1/sqrt(48)
    const long headCol = (long)h * (3 * PH);

    // q pre-scaled, packed into 24 f32x2 pairs
    u64 q2[24];
    {
        const float* qptr = qkv + ((long)(b * TSEQ + qrow)) * NQKV + headCol;
        #pragma unroll
        for (int i = 0; i < 12; i++) {
            float4 v = *(const float4*)&qptr[i * 4];
            q2[2 * i + 0] = pk2(v.x * scale, v.y * scale);
            q2[2 * i + 1] = pk2(v.z * scale, v.w * scale);
        }
    }

    u64 o2[24];
    #pragma unroll
    for (int i = 0; i < 24; i++) o2[i] = 0ull;
    float mi = -1e30f;
    float l = 0.f;

    for (int kb = 0; kb < TSEQ; kb += 64) {
        for (int idx = tid; idx < 64 * 12; idx += 128) {
            const int r  = idx / 12;
            const int c4 = idx % 12;
            const float* src = qkv + ((long)(b * TSEQ + kb + r)) * NQKV + headCol;
            *(float4*)&Ks[r][c4 * 4] = *(const float4*)&src[PH + c4 * 4];
            *(float4*)&Vs[r][c4 * 4] = *(const float4*)&src[2 * PH + c4 * 4];
        }
        __syncthreads();

        #pragma unroll 1
        for (int j = 0; j < 64; j++) {
            const ulonglong2* kr = (const ulonglong2*)Ks[j];   // 12 x 16B chunks
            u64 acc0 = 0ull, acc1 = 0ull;
            #pragma unroll
            for (int c = 0; c < 12; c++) {
                ulonglong2 kc = kr[c];
                fma2(acc0, q2[2 * c + 0], kc.x);
                fma2(acc1, q2[2 * c + 1], kc.y);
            }
            float2 s01 = upk2(acc0);
            float2 s23 = upk2(acc1);
            float s = (s01.x + s01.y) + (s23.x + s23.y);

            if (s > mi) {                         // lazy rescale (rare)
                float corr = __expf(mi - s);
                mi = s;
                l *= corr;
                u64 corr2 = pk2(corr, corr);
                #pragma unroll
                for (int d = 0; d < 24; d++) mul2(o2[d], o2[d], corr2);
            }
            float p = __expf(s - mi);
            l += p;
            u64 p2 = pk2(p, p);

            const ulonglong2* vr = (const ulonglong2*)Vs[j];
            #pragma unroll
            for (int c = 0; c < 12; c++) {
                ulonglong2 vc = vr[c];
                fma2(o2[2 * c + 0], p2, vc.x);
                fma2(o2[2 * c + 1], p2, vc.y);
            }
        }
        __syncthreads();
    }

    const float inv_l = 1.0f / l;
    float* optr = out + ((long)(b * TSEQ + qrow)) * DIMV + (long)h * PH;
    #pragma unroll
    for (int c = 0; c < 12; c++) {
        float2 lo = upk2(o2[2 * c + 0]);
        float2 hi = upk2(o2[2 * c + 1]);
        float4 v = make_float4(lo.x * inv_l, lo.y * inv_l,
                               hi.x * inv_l, hi.y * inv_l);
        *(float4*)&optr[c * 4] = v;
    }
}

// ---------------------------------------------------------------------------
extern "C" void kernel_launch(void* const* d_in, const int* in_sizes, int n_in,
                              void* d_out, int out_size)
{
    const float* x     = (const float*)d_in[0];
    const float* w_in  = (const float*)d_in[1];
    const float* b_in  = (const float*)d_in[2];
    const float* w_out = (const float*)d_in[3];
    const float* b_out = (const float*)d_in[4];
    float* out = (float*)d_out;

    float* qkv = nullptr;
    float* att = nullptr;
    cudaGetSymbolAddress((void**)&qkv, g_qkv);
    cudaGetSymbolAddress((void**)&att, g_att);

    // 1) QKV projection: (8192,768) @ (768,2304) + b_in
    {
        dim3 grid(NQKV / 128, MTOT / 128);
        gemm_bias_kernel<<<grid, 256>>>(x, w_in, b_in, qkv, MTOT, NQKV, DIMV);
    }

    // 2) Attention
    {
        dim3 grid(TSEQ / 128, BATCH * NHEAD);
        attn_kernel<<<grid, 128>>>(qkv, att);
    }

    // 3) Output projection: (8192,768) @ (768,768) + b_out
    {
        dim3 grid(DIMV / 128, MTOT / 128);
        gemm_bias_kernel<<<grid, 256>>>(att, w_out, b_out, out, MTOT, DIMV, DIMV);
    }
}